// round 1
// baseline (speedup 1.0000x reference)
#include <cuda_runtime.h>
#include <math.h>

#define N0 50000
#define N1 12500
#define N2 3125
#define E0C 800000
#define E1C 200000
#define E2C 50000
#define NNZC 200000

// ---------------- scratch (allocation-free: __device__ globals) ----------------
__device__ float g_agg6[N0 * 6];
__device__ float g_agg [N0 * 128];
__device__ float g_h1  [N0 * 128];
__device__ float g_h2  [N0 * 128];
__device__ float g_e0  [N0 * 96];
__device__ float g_e1  [N1 * 96];
__device__ float g_e2  [N2 * 96];
__device__ float g_i1  [N0 * 96];
__device__ float g_i2  [N0 * 96];

static inline int cdiv(int a, int b) { return (a + b - 1) / b; }

// ---------------- kernels ----------------

__global__ void zero_kernel(float* __restrict__ p, int n) {
    int i = blockIdx.x * blockDim.x + threadIdx.x;
    if (i < n) p[i] = 0.f;
}

// segment_sum of x[src] (6 features) into agg6[dst]
__global__ void scatter6_kernel(const float* __restrict__ x, const int* __restrict__ ei,
                                int E, float* __restrict__ agg) {
    int e = blockIdx.x * blockDim.x + threadIdx.x;
    if (e >= E) return;
    int s = ei[e];
    int d = ei[E + e];
#pragma unroll
    for (int j = 0; j < 6; j++)
        atomicAdd(&agg[d * 6 + j], x[s * 6 + j]);
}

// h1 = relu(agg6 @ Wrel(6x128) + brel + x @ Wroot(6x128)); block=128 thr, 32 nodes/block
__global__ void conv1_kernel(const float* __restrict__ x, const float* __restrict__ agg6,
                             const float* __restrict__ Wrel, const float* __restrict__ brel,
                             const float* __restrict__ Wroot, float* __restrict__ h1, int n) {
    __shared__ float sx[32 * 6];
    __shared__ float sa[32 * 6];
    int base = blockIdx.x * 32;
    int cnt = n - base; if (cnt > 32) cnt = 32;
    int t = threadIdx.x;
    for (int idx = t; idx < cnt * 6; idx += 128) {
        sx[idx] = x[base * 6 + idx];
        sa[idx] = agg6[base * 6 + idx];
    }
    __syncthreads();
    float wrel[6], wroot[6];
#pragma unroll
    for (int k = 0; k < 6; k++) { wrel[k] = Wrel[k * 128 + t]; wroot[k] = Wroot[k * 128 + t]; }
    float b = brel[t];
    for (int j = 0; j < cnt; j++) {
        float acc = b;
#pragma unroll
        for (int k = 0; k < 6; k++)
            acc = fmaf(sa[j * 6 + k], wrel[k], fmaf(sx[j * 6 + k], wroot[k], acc));
        h1[(base + j) * 128 + t] = fmaxf(acc, 0.f);
    }
}

// segment_sum of h[src] (128 features) into agg[dst]; one warp per edge, vector RED
__global__ void scatter128_kernel(const float* __restrict__ h, const int* __restrict__ ei,
                                  int E, float* __restrict__ agg) {
    int w = (blockIdx.x * blockDim.x + threadIdx.x) >> 5;
    int lane = threadIdx.x & 31;
    if (w >= E) return;
    int s = ei[w];
    int d = ei[E + w];
    float4 v = *(const float4*)(h + (size_t)s * 128 + lane * 4);
    atomicAdd((float4*)(agg + (size_t)d * 128 + lane * 4), v);
}

// out = relu(in1 @ W1(128x128) + b + in2 @ W2(128x128))
// block = 256 threads (8 warps); tile = 128 nodes; warp -> 16 nodes; lane -> 4 features
__global__ void __launch_bounds__(256) conv2_kernel(
    const float* __restrict__ in1, const float* __restrict__ in2,
    const float* __restrict__ W1, const float* __restrict__ W2,
    const float* __restrict__ b, float* __restrict__ out, int n) {
    extern __shared__ float smem[];
    float* s1 = smem;           // [128][128]
    float* s2 = smem + 16384;   // [128][128]
    int base = blockIdx.x * 128;
    int cnt = n - base; if (cnt > 128) cnt = 128;
    int t = threadIdx.x;
    for (int idx = t * 4; idx < cnt * 128; idx += 256 * 4) {
        *(float4*)(s1 + idx) = *(const float4*)(in1 + (size_t)base * 128 + idx);
        *(float4*)(s2 + idx) = *(const float4*)(in2 + (size_t)base * 128 + idx);
    }
    __syncthreads();
    int warp = t >> 5, lane = t & 31;
    int f = lane * 4;
    int nb = warp * 16;
    float4 bias = *(const float4*)(b + f);
    float acc[16][4];
#pragma unroll
    for (int j = 0; j < 16; j++) {
        acc[j][0] = bias.x; acc[j][1] = bias.y; acc[j][2] = bias.z; acc[j][3] = bias.w;
    }
    for (int k = 0; k < 128; k++) {
        float4 w1 = *(const float4*)(W1 + k * 128 + f);
        float4 w2 = *(const float4*)(W2 + k * 128 + f);
#pragma unroll
        for (int j = 0; j < 16; j++) {
            float a1 = s1[(nb + j) * 128 + k];
            float a2 = s2[(nb + j) * 128 + k];
            acc[j][0] = fmaf(a1, w1.x, fmaf(a2, w2.x, acc[j][0]));
            acc[j][1] = fmaf(a1, w1.y, fmaf(a2, w2.y, acc[j][1]));
            acc[j][2] = fmaf(a1, w1.z, fmaf(a2, w2.z, acc[j][2]));
            acc[j][3] = fmaf(a1, w1.w, fmaf(a2, w2.w, acc[j][3]));
        }
    }
#pragma unroll
    for (int j = 0; j < 16; j++) {
        int node = nb + j;
        if (node < cnt) {
            float4 r;
            r.x = fmaxf(acc[j][0], 0.f);
            r.y = fmaxf(acc[j][1], 0.f);
            r.z = fmaxf(acc[j][2], 0.f);
            r.w = fmaxf(acc[j][3], 0.f);
            *(float4*)(out + (size_t)(base + node) * 128 + f) = r;
        }
    }
}

// out = in @ W(128x96) + b; same tiling as conv2, lanes with f>=96 idle for compute
__global__ void __launch_bounds__(256) lin_kernel(
    const float* __restrict__ in, const float* __restrict__ W,
    const float* __restrict__ b, float* __restrict__ out, int n) {
    extern __shared__ float smem[];  // [128][128]
    int base = blockIdx.x * 128;
    int cnt = n - base; if (cnt > 128) cnt = 128;
    int t = threadIdx.x;
    for (int idx = t * 4; idx < cnt * 128; idx += 256 * 4)
        *(float4*)(smem + idx) = *(const float4*)(in + (size_t)base * 128 + idx);
    __syncthreads();
    int warp = t >> 5, lane = t & 31;
    int f = lane * 4;
    int nb = warp * 16;
    if (f < 96) {
        float4 bias = *(const float4*)(b + f);
        float acc[16][4];
#pragma unroll
        for (int j = 0; j < 16; j++) {
            acc[j][0] = bias.x; acc[j][1] = bias.y; acc[j][2] = bias.z; acc[j][3] = bias.w;
        }
        for (int k = 0; k < 128; k++) {
            float4 w = *(const float4*)(W + k * 96 + f);
#pragma unroll
            for (int j = 0; j < 16; j++) {
                float a = smem[(nb + j) * 128 + k];
                acc[j][0] = fmaf(a, w.x, acc[j][0]);
                acc[j][1] = fmaf(a, w.y, acc[j][1]);
                acc[j][2] = fmaf(a, w.z, acc[j][2]);
                acc[j][3] = fmaf(a, w.w, acc[j][3]);
            }
        }
#pragma unroll
        for (int j = 0; j < 16; j++) {
            int node = nb + j;
            if (node < cnt) {
                float4 r = make_float4(acc[j][0], acc[j][1], acc[j][2], acc[j][3]);
                *(float4*)(out + (size_t)(base + node) * 96 + f) = r;
            }
        }
    }
}

// i_acc[row] += val * e[col]  over nnz entries; one warp per nnz, lanes 0..23 (96 feats)
__global__ void interp_kernel(const float* __restrict__ e, const int* __restrict__ rows,
                              const int* __restrict__ cols, const float* __restrict__ vals,
                              int nnz, float* __restrict__ acc) {
    int w = (blockIdx.x * blockDim.x + threadIdx.x) >> 5;
    int lane = threadIdx.x & 31;
    if (w >= nnz || lane >= 24) return;
    int r = rows[w];
    int c = cols[w];
    float v = vals[w];
    float4 x = *(const float4*)(e + (size_t)c * 96 + lane * 4);
    float4 y = make_float4(x.x * v, x.y * v, x.z * v, x.w * v);
    atomicAdd((float4*)(acc + (size_t)r * 96 + lane * 4), y);
}

// decoder: per node, per branch i: h = elu([e0seg|i1seg|i2seg] @ W0_i + b0_i); out = h@Wout_i + bout_i
// one warp per node, lane -> 2 of 64 hidden units
__global__ void dec_kernel(const float* __restrict__ e0, const float* __restrict__ i1,
                           const float* __restrict__ i2,
                           const float* __restrict__ W0, const float* __restrict__ b0,
                           const float* __restrict__ Wout, const float* __restrict__ bout,
                           float* __restrict__ out, int n) {
    int w = (blockIdx.x * blockDim.x + threadIdx.x) >> 5;
    int lane = threadIdx.x & 31;
    if (w >= n) return;
#pragma unroll
    for (int br = 0; br < 3; br++) {
        const float* W = W0 + br * 96 * 64;
        float h0 = b0[br * 64 + 2 * lane];
        float h1 = b0[br * 64 + 2 * lane + 1];
        int ibase = w * 96 + br * 32;
#pragma unroll
        for (int part = 0; part < 3; part++) {
            const float* src = (part == 0) ? e0 : ((part == 1) ? i1 : i2);
            const float* Wp = W + part * 32 * 64;
            for (int o = 0; o < 32; o++) {
                float v = src[ibase + o];
                float2 wk = *(const float2*)(Wp + o * 64 + 2 * lane);
                h0 = fmaf(v, wk.x, h0);
                h1 = fmaf(v, wk.y, h1);
            }
        }
        h0 = (h0 > 0.f) ? h0 : expm1f(h0);
        h1 = (h1 > 0.f) ? h1 : expm1f(h1);
        float2 wo = *(const float2*)(Wout + br * 64 + 2 * lane);
        float r = h0 * wo.x + h1 * wo.y;
#pragma unroll
        for (int s = 16; s > 0; s >>= 1)
            r += __shfl_xor_sync(0xffffffff, r, s);
        if (lane == 0) out[w * 3 + br] = r + bout[br];
    }
}

// ---------------- host orchestration ----------------

extern "C" void kernel_launch(void* const* d_in, const int* in_sizes, int n_in,
                              void* d_out, int out_size) {
    const float* x[3]  = { (const float*)d_in[0], (const float*)d_in[1], (const float*)d_in[2] };
    const int*   ei[3] = { (const int*)d_in[3], (const int*)d_in[4], (const int*)d_in[5] };
    const int*   A1r = (const int*)d_in[6];
    const int*   A1c = (const int*)d_in[7];
    const float* A1v = (const float*)d_in[8];
    const int*   A2r = (const int*)d_in[9];
    const int*   A2c = (const int*)d_in[10];
    const float* A2v = (const float*)d_in[11];
    const float* c1Wrel  = (const float*)d_in[12];
    const float* c1brel  = (const float*)d_in[13];
    const float* c1Wroot = (const float*)d_in[14];
    const float* c2Wrel  = (const float*)d_in[15];
    const float* c2brel  = (const float*)d_in[16];
    const float* c2Wroot = (const float*)d_in[17];
    const float* linW = (const float*)d_in[18];
    const float* linb = (const float*)d_in[19];
    const float* dW0   = (const float*)d_in[20];
    const float* db0   = (const float*)d_in[21];
    const float* dWout = (const float*)d_in[22];
    const float* dbout = (const float*)d_in[23];
    float* out = (float*)d_out;

    void* p;
    cudaGetSymbolAddress(&p, g_agg6); float* agg6 = (float*)p;
    cudaGetSymbolAddress(&p, g_agg);  float* agg  = (float*)p;
    cudaGetSymbolAddress(&p, g_h1);   float* h1   = (float*)p;
    cudaGetSymbolAddress(&p, g_h2);   float* h2   = (float*)p;
    cudaGetSymbolAddress(&p, g_e0);   float* e0   = (float*)p;
    cudaGetSymbolAddress(&p, g_e1);   float* e1   = (float*)p;
    cudaGetSymbolAddress(&p, g_e2);   float* e2   = (float*)p;
    cudaGetSymbolAddress(&p, g_i1);   float* i1b  = (float*)p;
    cudaGetSymbolAddress(&p, g_i2);   float* i2b  = (float*)p;

    cudaFuncSetAttribute(conv2_kernel, cudaFuncAttributeMaxDynamicSharedMemorySize, 131072);
    cudaFuncSetAttribute(lin_kernel,   cudaFuncAttributeMaxDynamicSharedMemorySize, 65536);

    const int ncnt[3] = { N0, N1, N2 };
    const int ecnt[3] = { E0C, E1C, E2C };
    float* evec[3] = { e0, e1, e2 };

    for (int i = 0; i < 3; i++) {
        int n = ncnt[i], E = ecnt[i];
        zero_kernel<<<cdiv(n * 6, 256), 256>>>(agg6, n * 6);
        scatter6_kernel<<<cdiv(E, 256), 256>>>(x[i], ei[i], E, agg6);
        conv1_kernel<<<cdiv(n, 32), 128>>>(x[i], agg6,
                                           c1Wrel + i * 6 * 128, c1brel + i * 128,
                                           c1Wroot + i * 6 * 128, h1, n);
        zero_kernel<<<cdiv(n * 128, 256), 256>>>(agg, n * 128);
        scatter128_kernel<<<cdiv(E * 32, 256), 256>>>(h1, ei[i], E, agg);
        conv2_kernel<<<cdiv(n, 128), 256, 131072>>>(agg, h1,
                                                    c2Wrel + i * 128 * 128,
                                                    c2Wroot + i * 128 * 128,
                                                    c2brel + i * 128, h2, n);
        lin_kernel<<<cdiv(n, 128), 256, 65536>>>(h2, linW + i * 128 * 96,
                                                 linb + i * 96, evec[i], n);
    }

    zero_kernel<<<cdiv(N0 * 96, 256), 256>>>(i1b, N0 * 96);
    zero_kernel<<<cdiv(N0 * 96, 256), 256>>>(i2b, N0 * 96);
    interp_kernel<<<cdiv(NNZC * 32, 256), 256>>>(e1, A1r, A1c, A1v, NNZC, i1b);
    interp_kernel<<<cdiv(NNZC * 32, 256), 256>>>(e2, A2r, A2c, A2v, NNZC, i2b);
    dec_kernel<<<cdiv(N0 * 32, 256), 256>>>(e0, i1b, i2b, dW0, db0, dWout, dbout, out, N0);
}